// round 12
// baseline (speedup 1.0000x reference)
#include <cuda_runtime.h>
#include <cuda_fp16.h>
#include <cstdint>

#define NROWS 8192
#define DIN   512
#define DOUT  512

// ---------------- shared gemm constants ----------------
#define CTAM 128
#define CTAN 256
#define CTAK 32
#define NSTAGE 4
#define ROWB 80                     // fp16 row: 32 halves data + 16B pad
#define A16BYTES (CTAM * ROWB)      // 10240
#define BBYTES (CTAN * ROWB)        // 20480

// gemm1 (fp32 A staging): A32 row = 128B data + 16B pad
#define ROWA32 144
#define A32BYTES (CTAM * ROWA32)    // 18432
#define STAGEB1 (A32BYTES + BBYTES) // 38912
#define A16OFF (STAGEB1 * NSTAGE)   // 155648
#define DYN_SMEM1 (A16OFF + 2 * A16BYTES)  // 176128

// gemm2 (fp16 A, R4 layout)
#define STAGEB2 (A16BYTES + BBYTES) // 30720
#define DYN_SMEM2 (STAGEB2 * NSTAGE)// 122880

#define NT1 (NROWS / CTAK)          // 256
#define NT2 (DIN / CTAK)            // 16

// Scratch (allocation-free)
__device__ float  g_deg[NROWS];
__device__ __half g_xsT[(size_t)DIN * NROWS];        // xsT[n][k] = half(d_k * x[k][n])
__device__ __half g_support[(size_t)NROWS * DIN];    // fp16 intermediate
__device__ __half g_Wh[(size_t)DOUT * DIN];          // fp16 weights [n][k]

// ======================= PTX helpers =======================
__device__ __forceinline__ uint32_t smem_u32(const void* p) {
    uint32_t a;
    asm("{ .reg .u64 t; cvta.to.shared.u64 t, %1; cvt.u32.u64 %0, t; }" : "=r"(a) : "l"(p));
    return a;
}

__device__ __forceinline__ uint32_t h2_bits(__half2 h) {
    return *reinterpret_cast<uint32_t*>(&h);
}

#define CP_ASYNC16(dst, src) \
    asm volatile("cp.async.cg.shared.global [%0], [%1], 16;" :: "r"(dst), "l"(src))
#define CP_COMMIT() asm volatile("cp.async.commit_group;" ::: "memory")
#define CP_WAITG2() asm volatile("cp.async.wait_group 2;" ::: "memory")

#define LDSM4(r0, r1, r2, r3, addr)                                             \
    asm volatile("ldmatrix.sync.aligned.m8n8.x4.shared.b16 {%0,%1,%2,%3}, [%4];"\
                 : "=r"(r0), "=r"(r1), "=r"(r2), "=r"(r3) : "r"(addr))

#define MMA_F16(d, a, b0, b1)                                                   \
    asm volatile(                                                               \
        "mma.sync.aligned.m16n8k16.row.col.f32.f16.f16.f32 "                    \
        "{%0,%1,%2,%3}, {%4,%5,%6,%7}, {%8,%9}, {%0,%1,%2,%3};"                 \
        : "+f"((d)[0]), "+f"((d)[1]), "+f"((d)[2]), "+f"((d)[3])                \
        : "r"((a)[0]), "r"((a)[1]), "r"((a)[2]), "r"((a)[3]),                   \
          "r"(b0), "r"(b1))

// ---------------------------------------------------------------------------
// Kernel 1: d[i] = rsqrt(1 + sum_j adj[i][j])   (pure reduction, streaming)
// ---------------------------------------------------------------------------
__global__ __launch_bounds__(256) void rowsum_k(const float* __restrict__ adj) {
    const int row = blockIdx.x;
    const float4* p = reinterpret_cast<const float4*>(adj + (size_t)row * NROWS);
    float s = 0.f;
#pragma unroll 2
    for (int i = threadIdx.x; i < NROWS / 8; i += 256) {
        float4 v0 = __ldcs(&p[2 * i + 0]);
        float4 v1 = __ldcs(&p[2 * i + 1]);
        s += ((v0.x + v0.y) + (v0.z + v0.w)) + ((v1.x + v1.y) + (v1.z + v1.w));
    }
#pragma unroll
    for (int o = 16; o > 0; o >>= 1) s += __shfl_xor_sync(0xffffffffu, s, o);
    __shared__ float ws[8];
    if ((threadIdx.x & 31) == 0) ws[threadIdx.x >> 5] = s;
    __syncthreads();
    if (threadIdx.x == 0) {
        float t = 0.f;
#pragma unroll
        for (int i = 0; i < 8; i++) t += ws[i];
        g_deg[row] = rsqrtf(1.0f + t);
    }
}

// ---------------------------------------------------------------------------
// Kernel 2: xsT[n][k] = half( d_k * x[k][n] )   (scaled transpose)
// ---------------------------------------------------------------------------
__global__ __launch_bounds__(256) void scale_transpose_h(const float* __restrict__ x) {
    __shared__ float tile[32][33];
    const int kb = blockIdx.x * 32;
    const int nb = blockIdx.y * 32;
    const int tx = threadIdx.x & 31;
    const int ty = threadIdx.x >> 5;
#pragma unroll
    for (int i = 0; i < 32; i += 8) {
        int k = kb + ty + i;
        tile[ty + i][tx] = g_deg[k] * x[(size_t)k * DIN + nb + tx];
    }
    __syncthreads();
#pragma unroll
    for (int i = 0; i < 32; i += 8) {
        int n = nb + ty + i;
        g_xsT[(size_t)n * NROWS + kb + tx] = __float2half_rn(tile[tx][ty + i]);
    }
}

// ---------------------------------------------------------------------------
// Kernel 3: W fp32 -> fp16
// ---------------------------------------------------------------------------
__global__ __launch_bounds__(256) void w_convert(const float* __restrict__ W) {
    const int i = blockIdx.x * 256 + threadIdx.x;
    float4 v = reinterpret_cast<const float4*>(W)[i];
    __half2* d = reinterpret_cast<__half2*>(g_Wh) + 2 * i;
    d[0] = __floats2half2_rn(v.x, v.y);
    d[1] = __floats2half2_rn(v.z, v.w);
}

// ===========================================================================
// Common warp/fragment machinery (R4 geometry: 8 warps, 64x64 warp tiles)
// ===========================================================================
struct GemmCore {
    uint32_t sbase;
    int m0, n0, wm, wn, lane;
    uint32_t aoff, boff;
};

__device__ __forceinline__ void core_init(GemmCore& c, char* dyn, int bid) {
    const int tid = threadIdx.x;
    const int wid = tid >> 5;
    c.lane = tid & 31;
    c.m0 = (bid >> 1) * CTAM;
    c.n0 = (bid & 1) * CTAN;
    c.wm = (wid & 1) * 64;
    c.wn = (wid >> 1) * 64;
    c.sbase = smem_u32(dyn);
    const int l = c.lane;
    c.aoff = (uint32_t)((l & 15) * ROWB + ((l >> 4) & 1) * 16);
    c.boff = (uint32_t)(((l & 7) + ((l >> 4) & 1) * 8) * ROWB + ((l >> 3) & 1) * 16);
}

__device__ __forceinline__ void mma_all(float acc[4][8][4],
                                        uint32_t a[4][4], uint32_t b[8][2]) {
#pragma unroll
    for (int i = 0; i < 4; i++)
#pragma unroll
        for (int j = 0; j < 8; j++)
            MMA_F16(acc[i][j], a[i], b[j][0], b[j][1]);
}

// ===========================================================================
// gemm1: A = adj fp32 (converted in-kernel), B = g_xsT fp16
// ===========================================================================
// Load one k-tile: A as fp32 (1024 chunks), B as fp16 (1024 chunks).
__device__ __forceinline__ void load_tile1(const GemmCore& c,
                                           const float* __restrict__ adj, int t) {
    const int tid = threadIdx.x;
    const int k0 = t * CTAK;
    const uint32_t stA = c.sbase + (uint32_t)(t & (NSTAGE - 1)) * STAGEB1;
    const uint32_t stB = stA + A32BYTES;
#pragma unroll
    for (int i = 0; i < 4; i++) {
        int ch = tid + i * 256;
        int r = ch >> 3, q = ch & 7;
        CP_ASYNC16(stA + (uint32_t)(r * ROWA32 + q * 16),
                   adj + (size_t)(c.m0 + r) * NROWS + k0 + q * 4);
    }
#pragma unroll
    for (int i = 0; i < 4; i++) {
        int ch = tid + i * 256;
        int r = ch >> 2, q = ch & 3;
        CP_ASYNC16(stB + (uint32_t)(r * ROWB + q * 16),
                   g_xsT + (size_t)(c.n0 + r) * NROWS + k0 + q * 8);
    }
}

// Convert A32 stage of tile t into A16 buffer bb. 512 out-chunks of 16B.
__device__ __forceinline__ void convert_a(char* dyn, int t, int bb) {
    const int tid = threadIdx.x;
    char* src = dyn + (size_t)(t & (NSTAGE - 1)) * STAGEB1;
    char* dst = dyn + A16OFF + (size_t)bb * A16BYTES;
#pragma unroll
    for (int i = 0; i < 2; i++) {
        int ch = tid + i * 256;
        int r = ch >> 2, q = ch & 3;
        const float4* s = reinterpret_cast<const float4*>(src + r * ROWA32 + q * 32);
        float4 f0 = s[0];
        float4 f1 = s[1];
        uint4 o;
        o.x = h2_bits(__floats2half2_rn(f0.x, f0.y));
        o.y = h2_bits(__floats2half2_rn(f0.z, f0.w));
        o.z = h2_bits(__floats2half2_rn(f1.x, f1.y));
        o.w = h2_bits(__floats2half2_rn(f1.z, f1.w));
        *reinterpret_cast<uint4*>(dst + r * ROWB + q * 16) = o;
    }
}

// Fragments for gemm1: A from A16 buffer bb, B from stage slot of tile t.
__device__ __forceinline__ void lds_frags1(const GemmCore& c, int t, int s, int bb,
                                           uint32_t a[4][4], uint32_t b[8][2]) {
    const uint32_t a16 = c.sbase + A16OFF + (uint32_t)bb * A16BYTES;
    const uint32_t stB = c.sbase + (uint32_t)(t & (NSTAGE - 1)) * STAGEB1 + A32BYTES;
#pragma unroll
    for (int i = 0; i < 4; i++)
        LDSM4(a[i][0], a[i][1], a[i][2], a[i][3],
              a16 + (uint32_t)((c.wm + 16 * i) * ROWB + s * 32) + c.aoff);
#pragma unroll
    for (int jp = 0; jp < 4; jp++)
        LDSM4(b[2 * jp][0], b[2 * jp][1], b[2 * jp + 1][0], b[2 * jp + 1][1],
              stB + (uint32_t)((c.wn + 16 * jp) * ROWB + s * 32) + c.boff);
}

// ---------------------------------------------------------------------------
// Kernel 4: support = d_i * ( adj @ xsT^T + d_i * x_i )   -> fp16
// ---------------------------------------------------------------------------
__global__ __launch_bounds__(256, 1) void gemm1_h(const float* __restrict__ adj,
                                                  const float* __restrict__ x) {
    extern __shared__ __align__(128) char dyn[];
    GemmCore c;
    core_init(c, dyn, blockIdx.x);

    float acc[4][8][4];
#pragma unroll
    for (int i = 0; i < 4; i++)
#pragma unroll
        for (int j = 0; j < 8; j++)
#pragma unroll
            for (int q = 0; q < 4; q++) acc[i][j][q] = 0.f;

    // prologue: tiles 0..2
#pragma unroll
    for (int s = 0; s < NSTAGE - 1; s++) {
        load_tile1(c, adj, s);
        CP_COMMIT();
    }
    CP_WAITG2();                 // tile 0 resident
    convert_a(dyn, 0, 0);        // A16 buf 0 <- tile 0
    __syncthreads();             // publish conversion + cp.async data

    uint32_t a0[4][4], b0[8][2], a1[4][4], b1[8][2];
    lds_frags1(c, 0, 0, 0, a0, b0);

    for (int t = 0; t < NT1; t++) {
        const int bb = t & 1;
        if (t + NSTAGE - 1 < NT1)
            load_tile1(c, adj, t + NSTAGE - 1);
        CP_COMMIT();                       // uniform group count per iter
        lds_frags1(c, t, 1, bb, a1, b1);   // overlaps mma
        mma_all(acc, a0, b0);
        if (t + 1 < NT1) {
            CP_WAITG2();                   // tile t+1 (A32+B) resident
            convert_a(dyn, t + 1, bb ^ 1); // overlaps nothing it shouldn't:
                                           // buf bb^1's last reader ran before
                                           // the PREVIOUS barrier.
            __syncthreads();               // publish A16 buf + retire stage reads
            lds_frags1(c, t + 1, 0, bb ^ 1, a0, b0);
        }
        mma_all(acc, a1, b1);
    }

    // epilogue: support = half( d_m * (acc + d_m * x) )
    const int g = c.lane >> 2, tg = c.lane & 3;
#pragma unroll
    for (int i = 0; i < 4; i++) {
        const int r0 = c.m0 + c.wm + 16 * i + g;
        const int r1 = r0 + 8;
        const float d0 = g_deg[r0], d1 = g_deg[r1];
#pragma unroll
        for (int j = 0; j < 8; j++) {
            const int col = c.n0 + c.wn + 8 * j + 2 * tg;
            float2 x0 = *reinterpret_cast<const float2*>(&x[(size_t)r0 * DIN + col]);
            float2 x1 = *reinterpret_cast<const float2*>(&x[(size_t)r1 * DIN + col]);
            __half2 h0 = __floats2half2_rn(d0 * (acc[i][j][0] + d0 * x0.x),
                                           d0 * (acc[i][j][1] + d0 * x0.y));
            __half2 h1 = __floats2half2_rn(d1 * (acc[i][j][2] + d1 * x1.x),
                                           d1 * (acc[i][j][3] + d1 * x1.y));
            *reinterpret_cast<__half2*>(&g_support[(size_t)r0 * DIN + col]) = h0;
            *reinterpret_cast<__half2*>(&g_support[(size_t)r1 * DIN + col]) = h1;
        }
    }
}

// ===========================================================================
// gemm2 machinery (EXACT R4 fp16 path)
// ===========================================================================
__device__ __forceinline__ void load_tile2(const GemmCore& c,
                                           const __half* __restrict__ Ag,
                                           const __half* __restrict__ Bg, int t) {
    const int tid = threadIdx.x;
    const int k0 = t * CTAK;
    const uint32_t stA = c.sbase + (uint32_t)(t & (NSTAGE - 1)) * STAGEB2;
    const uint32_t stB = stA + A16BYTES;
#pragma unroll
    for (int i = 0; i < 2; i++) {
        int ch = tid + i * 256;
        int r = ch >> 2, q = ch & 3;
        CP_ASYNC16(stA + (uint32_t)(r * ROWB + q * 16),
                   Ag + (size_t)(c.m0 + r) * DIN + k0 + q * 8);
    }
#pragma unroll
    for (int i = 0; i < 4; i++) {
        int ch = tid + i * 256;
        int r = ch >> 2, q = ch & 3;
        CP_ASYNC16(stB + (uint32_t)(r * ROWB + q * 16),
                   Bg + (size_t)(c.n0 + r) * DIN + k0 + q * 8);
    }
}

__device__ __forceinline__ void lds_frags2(const GemmCore& c, int t, int s,
                                           uint32_t a[4][4], uint32_t b[8][2]) {
    const uint32_t stA = c.sbase + (uint32_t)(t & (NSTAGE - 1)) * STAGEB2;
    const uint32_t stB = stA + A16BYTES;
#pragma unroll
    for (int i = 0; i < 4; i++)
        LDSM4(a[i][0], a[i][1], a[i][2], a[i][3],
              stA + (uint32_t)((c.wm + 16 * i) * ROWB + s * 32) + c.aoff);
#pragma unroll
    for (int jp = 0; jp < 4; jp++)
        LDSM4(b[2 * jp][0], b[2 * jp][1], b[2 * jp + 1][0], b[2 * jp + 1][1],
              stB + (uint32_t)((c.wn + 16 * jp) * ROWB + s * 32) + c.boff);
}

// ---------------------------------------------------------------------------
// Kernel 5: out = relu(support @ Wh^T + b)   -> fp32
// ---------------------------------------------------------------------------
__global__ __launch_bounds__(256, 1) void gemm2_h(const float* __restrict__ bias,
                                                  float* __restrict__ out) {
    extern __shared__ __align__(128) char dyn[];
    GemmCore c;
    core_init(c, dyn, blockIdx.x);

    float acc[4][8][4];
#pragma unroll
    for (int i = 0; i < 4; i++)
#pragma unroll
        for (int j = 0; j < 8; j++)
#pragma unroll
            for (int q = 0; q < 4; q++) acc[i][j][q] = 0.f;

#pragma unroll
    for (int s = 0; s < NSTAGE - 1; s++) {
        load_tile2(c, g_support, g_Wh, s);
        CP_COMMIT();
    }
    CP_WAITG2();
    __syncthreads();

    uint32_t a0[4][4], b0[8][2], a1[4][4], b1[8][2];
    lds_frags2(c, 0, 0, a0, b0);

    for (int t = 0; t < NT2; t++) {
        if (t + NSTAGE - 1 < NT2)
            load_tile2(c, g_support, g_Wh, t + NSTAGE - 1);
        CP_COMMIT();
        lds_frags2(c, t, 1, a1, b1);
        mma_all(acc, a0, b0);
        if (t + 1 < NT2) {
            CP_WAITG2();
            __syncthreads();
            lds_frags2(c, t + 1, 0, a0, b0);
        }
        mma_all(acc, a1, b1);
    }

    const int g = c.lane >> 2, tg = c.lane & 3;
#pragma unroll
    for (int i = 0; i < 4; i++) {
        const int r0 = c.m0 + c.wm + 16 * i + g;
        const int r1 = r0 + 8;
#pragma unroll
        for (int j = 0; j < 8; j++) {
            const int col = c.n0 + c.wn + 8 * j + 2 * tg;
            float2 bv = *reinterpret_cast<const float2*>(&bias[col]);
            float2 o0, o1;
            o0.x = fmaxf(acc[i][j][0] + bv.x, 0.f);
            o0.y = fmaxf(acc[i][j][1] + bv.y, 0.f);
            o1.x = fmaxf(acc[i][j][2] + bv.x, 0.f);
            o1.y = fmaxf(acc[i][j][3] + bv.y, 0.f);
            *reinterpret_cast<float2*>(&out[(size_t)r0 * DOUT + col]) = o0;
            *reinterpret_cast<float2*>(&out[(size_t)r1 * DOUT + col]) = o1;
        }
    }
}

// ---------------------------------------------------------------------------
extern "C" void kernel_launch(void* const* d_in, const int* in_sizes, int n_in,
                              void* d_out, int out_size) {
    const float* x = nullptr;
    const float* adj = nullptr;
    const float* W = nullptr;
    const float* b = nullptr;
    for (int i = 0; i < n_in; i++) {
        long sz = (long)in_sizes[i];
        if (sz == (long)NROWS * NROWS)      adj = (const float*)d_in[i];
        else if (sz == (long)NROWS * DIN)   x   = (const float*)d_in[i];
        else if (sz == (long)DIN * DOUT)    W   = (const float*)d_in[i];
        else if (sz == (long)DOUT)          b   = (const float*)d_in[i];
    }
    float* out = (float*)d_out;

    cudaFuncSetAttribute(gemm1_h, cudaFuncAttributeMaxDynamicSharedMemorySize, DYN_SMEM1);
    cudaFuncSetAttribute(gemm2_h, cudaFuncAttributeMaxDynamicSharedMemorySize, DYN_SMEM2);

    rowsum_k<<<NROWS, 256>>>(adj);
    scale_transpose_h<<<dim3(NROWS / 32, DIN / 32), 256>>>(x);
    w_convert<<<(DOUT * DIN / 4) / 256, 256>>>(W);
    gemm1_h<<<(NROWS / CTAM) * (DIN / CTAN), 256, DYN_SMEM1>>>(adj, x);
    gemm2_h<<<(NROWS / CTAM) * (DOUT / CTAN), 256, DYN_SMEM2>>>(b, out);
}

// round 13
// speedup vs baseline: 1.1551x; 1.1551x over previous
#include <cuda_runtime.h>
#include <cuda_fp16.h>
#include <cstdint>

#define NROWS 8192
#define DIN   512
#define DOUT  512

// ---------------- fp16 mma.sync gemm tiling (R4 geometry) ----------------
#define CTAM 128
#define CTAN 256
#define CTAK 32
#define NSTAGE 4
#define ROWB 80                     // 32 halves data + 16B pad
#define ABYTES (CTAM * ROWB)        // 10240
#define BBYTES (CTAN * ROWB)        // 20480
#define STAGEB (ABYTES + BBYTES)    // 30720
#define DYN_SMEM (STAGEB * NSTAGE)  // 122880

#define NT1 (NROWS / CTAK)          // 256 k-tiles for gemm1
#define NT2 (DIN / CTAK)            // 16 k-tiles for gemm2

// Scratch (allocation-free)
__device__ __half g_adj_h[(size_t)NROWS * NROWS];    // fp16 adjacency
__device__ float  g_deg[NROWS];
__device__ __half g_xsT[(size_t)DIN * NROWS];        // xsT[n][k] = half(d_k * x[k][n])
__device__ __half g_support[(size_t)NROWS * DIN];    // fp16 intermediate
__device__ __half g_Wh[(size_t)DOUT * DIN];          // fp16 weights [n][k]

// ======================= PTX helpers =======================
__device__ __forceinline__ uint32_t smem_u32(const void* p) {
    uint32_t a;
    asm("{ .reg .u64 t; cvta.to.shared.u64 t, %1; cvt.u32.u64 %0, t; }" : "=r"(a) : "l"(p));
    return a;
}

__device__ __forceinline__ uint32_t h2_bits(__half2 h) {
    return *reinterpret_cast<uint32_t*>(&h);
}

#define CP_ASYNC16(dst, src) \
    asm volatile("cp.async.cg.shared.global [%0], [%1], 16;" :: "r"(dst), "l"(src))
#define CP_COMMIT() asm volatile("cp.async.commit_group;" ::: "memory")
#define CP_WAITG2() asm volatile("cp.async.wait_group 2;" ::: "memory")

#define LDSM4(r0, r1, r2, r3, addr)                                             \
    asm volatile("ldmatrix.sync.aligned.m8n8.x4.shared.b16 {%0,%1,%2,%3}, [%4];"\
                 : "=r"(r0), "=r"(r1), "=r"(r2), "=r"(r3) : "r"(addr))

#define MMA_F16(d, a, b0, b1)                                                   \
    asm volatile(                                                               \
        "mma.sync.aligned.m16n8k16.row.col.f32.f16.f16.f32 "                    \
        "{%0,%1,%2,%3}, {%4,%5,%6,%7}, {%8,%9}, {%0,%1,%2,%3};"                 \
        : "+f"((d)[0]), "+f"((d)[1]), "+f"((d)[2]), "+f"((d)[3])                \
        : "r"((a)[0]), "r"((a)[1]), "r"((a)[2]), "r"((a)[3]),                   \
          "r"(b0), "r"(b1))

// ---------------------------------------------------------------------------
// Kernel 1: d[i] = rsqrt(1 + sum_j adj[i][j])  AND  g_adj_h = half(adj)
//   Streaming loads/stores, 4x unroll for MLP.
// ---------------------------------------------------------------------------
__global__ __launch_bounds__(256) void rowsum_convert(const float* __restrict__ adj) {
    const int row = blockIdx.x;
    const float4* p = reinterpret_cast<const float4*>(adj + (size_t)row * NROWS);
    uint4* dst = reinterpret_cast<uint4*>(g_adj_h + (size_t)row * NROWS);
    float s = 0.f;
    // NROWS/8 = 1024 uint4-chunks per row; 256 threads x 4 iters, unrolled x4.
#pragma unroll 4
    for (int i = threadIdx.x; i < NROWS / 8; i += 256) {
        float4 v0 = __ldcs(&p[2 * i + 0]);
        float4 v1 = __ldcs(&p[2 * i + 1]);
        s += ((v0.x + v0.y) + (v0.z + v0.w)) + ((v1.x + v1.y) + (v1.z + v1.w));
        uint4 o;
        o.x = h2_bits(__floats2half2_rn(v0.x, v0.y));
        o.y = h2_bits(__floats2half2_rn(v0.z, v0.w));
        o.z = h2_bits(__floats2half2_rn(v1.x, v1.y));
        o.w = h2_bits(__floats2half2_rn(v1.z, v1.w));
        __stcs(&dst[i], o);
    }
#pragma unroll
    for (int o = 16; o > 0; o >>= 1) s += __shfl_xor_sync(0xffffffffu, s, o);
    __shared__ float ws[8];
    if ((threadIdx.x & 31) == 0) ws[threadIdx.x >> 5] = s;
    __syncthreads();
    if (threadIdx.x == 0) {
        float t = 0.f;
#pragma unroll
        for (int i = 0; i < 8; i++) t += ws[i];
        g_deg[row] = rsqrtf(1.0f + t);
    }
}

// ---------------------------------------------------------------------------
// Kernel 2: xsT[n][k] = half( d_k * x[k][n] )   (scaled transpose)
// ---------------------------------------------------------------------------
__global__ __launch_bounds__(256) void scale_transpose_h(const float* __restrict__ x) {
    __shared__ float tile[32][33];
    const int kb = blockIdx.x * 32;
    const int nb = blockIdx.y * 32;
    const int tx = threadIdx.x & 31;
    const int ty = threadIdx.x >> 5;
#pragma unroll
    for (int i = 0; i < 32; i += 8) {
        int k = kb + ty + i;
        tile[ty + i][tx] = g_deg[k] * x[(size_t)k * DIN + nb + tx];
    }
    __syncthreads();
#pragma unroll
    for (int i = 0; i < 32; i += 8) {
        int n = nb + ty + i;
        g_xsT[(size_t)n * NROWS + kb + tx] = __float2half_rn(tile[tx][ty + i]);
    }
}

// ---------------------------------------------------------------------------
// Kernel 3: W fp32 -> fp16
// ---------------------------------------------------------------------------
__global__ __launch_bounds__(256) void w_convert(const float* __restrict__ W) {
    const int i = blockIdx.x * 256 + threadIdx.x;
    float4 v = reinterpret_cast<const float4*>(W)[i];
    __half2* d = reinterpret_cast<__half2*>(g_Wh) + 2 * i;
    d[0] = __floats2half2_rn(v.x, v.y);
    d[1] = __floats2half2_rn(v.z, v.w);
}

// ===========================================================================
// Gemm core (EXACT R4): CTA 128x256, 8 warps (2m x 4n) of 64x64, BK=32,
// 4-stage cp.async, double-buffered ldmatrix fragments.
// ===========================================================================
struct GemmCore {
    uint32_t sbase;
    int m0, n0, wm, wn, lane;
    uint32_t aoff, boff;
};

__device__ __forceinline__ void core_init(GemmCore& c, char* dyn, int bid) {
    const int tid = threadIdx.x;
    const int wid = tid >> 5;
    c.lane = tid & 31;
    c.m0 = (bid >> 1) * CTAM;
    c.n0 = (bid & 1) * CTAN;
    c.wm = (wid & 1) * 64;
    c.wn = (wid >> 1) * 64;
    c.sbase = smem_u32(dyn);
    const int l = c.lane;
    c.aoff = (uint32_t)((l & 15) * ROWB + ((l >> 4) & 1) * 16);
    c.boff = (uint32_t)(((l & 7) + ((l >> 4) & 1) * 8) * ROWB + ((l >> 3) & 1) * 16);
}

__device__ __forceinline__ void load_tile(const GemmCore& c,
                                          const __half* __restrict__ Ag, int strideA,
                                          const __half* __restrict__ Bg, int strideB,
                                          int t) {
    const int tid = threadIdx.x;
    const int k0 = t * CTAK;
    const uint32_t stA = c.sbase + (uint32_t)(t & (NSTAGE - 1)) * STAGEB;
    const uint32_t stB = stA + ABYTES;
#pragma unroll
    for (int i = 0; i < 2; i++) {
        int ch = tid + i * 256;
        int r = ch >> 2, q = ch & 3;
        CP_ASYNC16(stA + (uint32_t)(r * ROWB + q * 16),
                   Ag + (size_t)(c.m0 + r) * strideA + k0 + q * 8);
    }
#pragma unroll
    for (int i = 0; i < 4; i++) {
        int ch = tid + i * 256;
        int r = ch >> 2, q = ch & 3;
        CP_ASYNC16(stB + (uint32_t)(r * ROWB + q * 16),
                   Bg + (size_t)(c.n0 + r) * strideB + k0 + q * 8);
    }
}

// Load all fragments for k-half s (s in {0,1}) of tile t.
__device__ __forceinline__ void lds_frags(const GemmCore& c, int t, int s,
                                          uint32_t a[4][4], uint32_t b[8][2]) {
    const uint32_t stA = c.sbase + (uint32_t)(t & (NSTAGE - 1)) * STAGEB;
    const uint32_t stB = stA + ABYTES;
#pragma unroll
    for (int i = 0; i < 4; i++)
        LDSM4(a[i][0], a[i][1], a[i][2], a[i][3],
              stA + (uint32_t)((c.wm + 16 * i) * ROWB + s * 32) + c.aoff);
#pragma unroll
    for (int jp = 0; jp < 4; jp++)
        LDSM4(b[2 * jp][0], b[2 * jp][1], b[2 * jp + 1][0], b[2 * jp + 1][1],
              stB + (uint32_t)((c.wn + 16 * jp) * ROWB + s * 32) + c.boff);
}

__device__ __forceinline__ void mma_all(float acc[4][8][4],
                                        uint32_t a[4][4], uint32_t b[8][2]) {
#pragma unroll
    for (int i = 0; i < 4; i++)
#pragma unroll
        for (int j = 0; j < 8; j++)
            MMA_F16(acc[i][j], a[i], b[j][0], b[j][1]);
}

// Pipelined mainloop shared by both gemms (EXACT R4 schedule).
__device__ __forceinline__ void gemm_mainloop(const GemmCore& c,
                                              const __half* __restrict__ Ag, int strideA,
                                              const __half* __restrict__ Bg, int strideB,
                                              int ntiles, float acc[4][8][4]) {
    // prologue: stages 0..2
#pragma unroll
    for (int s = 0; s < NSTAGE - 1; s++) {
        load_tile(c, Ag, strideA, Bg, strideB, s);
        CP_COMMIT();
    }
    CP_WAITG2();                 // tile 0 resident
    __syncthreads();

    uint32_t a0[4][4], b0[8][2], a1[4][4], b1[8][2];
    lds_frags(c, 0, 0, a0, b0);

    for (int t = 0; t < ntiles; t++) {
        if (t + NSTAGE - 1 < ntiles)
            load_tile(c, Ag, strideA, Bg, strideB, t + NSTAGE - 1);
        CP_COMMIT();                     // uniform group count per iter
        lds_frags(c, t, 1, a1, b1);      // overlaps with mma below
        mma_all(acc, a0, b0);
        if (t + 1 < ntiles) {
            CP_WAITG2();                 // tile t+1 resident
            __syncthreads();             // stage slot (t+3)&3 safe to refill next iter
            lds_frags(c, t + 1, 0, a0, b0);  // overlaps with mma below
        }
        mma_all(acc, a1, b1);
    }
}

// ---------------------------------------------------------------------------
// Kernel 4: support = d_i * ( adj_h @ xsT^T + d_i * x_i )   -> fp16
// ---------------------------------------------------------------------------
__global__ __launch_bounds__(256, 1) void gemm1_h(const float* __restrict__ x) {
    extern __shared__ __align__(128) char dyn[];
    GemmCore c;
    core_init(c, dyn, blockIdx.x);

    float acc[4][8][4];
#pragma unroll
    for (int i = 0; i < 4; i++)
#pragma unroll
        for (int j = 0; j < 8; j++)
#pragma unroll
            for (int q = 0; q < 4; q++) acc[i][j][q] = 0.f;

    gemm_mainloop(c, g_adj_h, NROWS, g_xsT, NROWS, NT1, acc);

    // epilogue: support = half( d_m * (acc + d_m * x) )
    const int g = c.lane >> 2, tg = c.lane & 3;
#pragma unroll
    for (int i = 0; i < 4; i++) {
        const int r0 = c.m0 + c.wm + 16 * i + g;
        const int r1 = r0 + 8;
        const float d0 = g_deg[r0], d1 = g_deg[r1];
#pragma unroll
        for (int j = 0; j < 8; j++) {
            const int col = c.n0 + c.wn + 8 * j + 2 * tg;
            float2 x0 = *reinterpret_cast<const float2*>(&x[(size_t)r0 * DIN + col]);
            float2 x1 = *reinterpret_cast<const float2*>(&x[(size_t)r1 * DIN + col]);
            __half2 h0 = __floats2half2_rn(d0 * (acc[i][j][0] + d0 * x0.x),
                                           d0 * (acc[i][j][1] + d0 * x0.y));
            __half2 h1 = __floats2half2_rn(d1 * (acc[i][j][2] + d1 * x1.x),
                                           d1 * (acc[i][j][3] + d1 * x1.y));
            *reinterpret_cast<__half2*>(&g_support[(size_t)r0 * DIN + col]) = h0;
            *reinterpret_cast<__half2*>(&g_support[(size_t)r1 * DIN + col]) = h1;
        }
    }
}

// ---------------------------------------------------------------------------
// Kernel 5: out = relu(support @ Wh^T + b)   -> fp32
// ---------------------------------------------------------------------------
__global__ __launch_bounds__(256, 1) void gemm2_h(const float* __restrict__ bias,
                                                  float* __restrict__ out) {
    extern __shared__ __align__(128) char dyn[];
    GemmCore c;
    core_init(c, dyn, blockIdx.x);

    float acc[4][8][4];
#pragma unroll
    for (int i = 0; i < 4; i++)
#pragma unroll
        for (int j = 0; j < 8; j++)
#pragma unroll
            for (int q = 0; q < 4; q++) acc[i][j][q] = 0.f;

    gemm_mainloop(c, g_support, DIN, g_Wh, DIN, NT2, acc);

    const int g = c.lane >> 2, tg = c.lane & 3;
#pragma unroll
    for (int i = 0; i < 4; i++) {
        const int r0 = c.m0 + c.wm + 16 * i + g;
        const int r1 = r0 + 8;
#pragma unroll
        for (int j = 0; j < 8; j++) {
            const int col = c.n0 + c.wn + 8 * j + 2 * tg;
            float2 bv = *reinterpret_cast<const float2*>(&bias[col]);
            float2 o0, o1;
            o0.x = fmaxf(acc[i][j][0] + bv.x, 0.f);
            o0.y = fmaxf(acc[i][j][1] + bv.y, 0.f);
            o1.x = fmaxf(acc[i][j][2] + bv.x, 0.f);
            o1.y = fmaxf(acc[i][j][3] + bv.y, 0.f);
            *reinterpret_cast<float2*>(&out[(size_t)r0 * DOUT + col]) = o0;
            *reinterpret_cast<float2*>(&out[(size_t)r1 * DOUT + col]) = o1;
        }
    }
}

// ---------------------------------------------------------------------------
extern "C" void kernel_launch(void* const* d_in, const int* in_sizes, int n_in,
                              void* d_out, int out_size) {
    const float* x = nullptr;
    const float* adj = nullptr;
    const float* W = nullptr;
    const float* b = nullptr;
    for (int i = 0; i < n_in; i++) {
        long sz = (long)in_sizes[i];
        if (sz == (long)NROWS * NROWS)      adj = (const float*)d_in[i];
        else if (sz == (long)NROWS * DIN)   x   = (const float*)d_in[i];
        else if (sz == (long)DIN * DOUT)    W   = (const float*)d_in[i];
        else if (sz == (long)DOUT)          b   = (const float*)d_in[i];
    }
    float* out = (float*)d_out;

    cudaFuncSetAttribute(gemm1_h, cudaFuncAttributeMaxDynamicSharedMemorySize, DYN_SMEM);
    cudaFuncSetAttribute(gemm2_h, cudaFuncAttributeMaxDynamicSharedMemorySize, DYN_SMEM);

    rowsum_convert<<<NROWS, 256>>>(adj);
    scale_transpose_h<<<dim3(NROWS / 32, DIN / 32), 256>>>(x);
    w_convert<<<(DOUT * DIN / 4) / 256, 256>>>(W);
    gemm1_h<<<(NROWS / CTAM) * (DIN / CTAN), 256, DYN_SMEM>>>(x);
    gemm2_h<<<(NROWS / CTAM) * (DOUT / CTAN), 256, DYN_SMEM>>>(b, out);
}